// round 14
// baseline (speedup 1.0000x reference)
#include <cuda_runtime.h>
#include <cuda_fp16.h>
#include <cstdint>

#define NN 100000
#define NE 1600000
#define NCH 64
#define EPS 1e-5f
#define BKT 64                                 // bucket capacity per node
#define GB  ((NN + 127) / 128)                 // 782 gemm blocks

// ---------------- scratch (device globals; no allocation allowed) ----------
__device__ int    g_cnt[NN];
__device__ float  g_dinv[NN];
__device__ int    g_csrS[(size_t)NN * BKT];    // padded buckets: src only
__device__ float  g_Y[(size_t)NN * NCH];
__device__ __half g_xh[(size_t)NN * NCH];      // fp16 shadow of x
__device__ __half g_T1h[(size_t)NN * NCH];     // fp16 Tx1 (per layer)
__device__ __half g_T2h[(size_t)NN * NCH];     // fp16 Tx2 (per layer)
__device__ __half g_Yh[(size_t)NN * NCH];      // fp16 relu(Y) layer1
__device__ float  g_part[2 * GB * NCH];
__device__ float  g_stats[2 * NCH];

// ---------------- init: zero counters + fp16 shadow of x -------------------
__global__ void k_init(const float* __restrict__ x) {
    int i = blockIdx.x * blockDim.x + threadIdx.x;
    if (i < NN) g_cnt[i] = 0;
    if (i < NN * NCH / 8) {
        float4 a = ((const float4*)x)[2 * i];
        float4 b = ((const float4*)x)[2 * i + 1];
        uint4 u;
        ((__half2*)&u)[0] = __floats2half2_rn(a.x, a.y);
        ((__half2*)&u)[1] = __floats2half2_rn(a.z, a.w);
        ((__half2*)&u)[2] = __floats2half2_rn(b.x, b.y);
        ((__half2*)&u)[3] = __floats2half2_rn(b.z, b.w);
        ((uint4*)g_xh)[i] = u;
    }
}

// ---------------- bucket fill: count + store src, 4 edges/thread -----------
// edge_index is int32 (JAX default x64-disabled demotes int64 -> int32)
__global__ void k_fill(const int* __restrict__ ei) {
    int i = blockIdx.x * blockDim.x + threadIdx.x;
    if (i < NE / 4) {
        int4 s4 = ((const int4*)ei)[i];
        int4 d4 = ((const int4*)(ei + NE))[i];
        int c0 = -1, c1 = -1, c2 = -1, c3 = -1;
        if ((unsigned)s4.x < NN && (unsigned)d4.x < NN)
            c0 = atomicAdd(&g_cnt[d4.x], 1);
        if ((unsigned)s4.y < NN && (unsigned)d4.y < NN)
            c1 = atomicAdd(&g_cnt[d4.y], 1);
        if ((unsigned)s4.z < NN && (unsigned)d4.z < NN)
            c2 = atomicAdd(&g_cnt[d4.z], 1);
        if ((unsigned)s4.w < NN && (unsigned)d4.w < NN)
            c3 = atomicAdd(&g_cnt[d4.w], 1);
        if (c0 >= 0 && c0 < BKT) g_csrS[(size_t)d4.x * BKT + c0] = s4.x;
        if (c1 >= 0 && c1 < BKT) g_csrS[(size_t)d4.y * BKT + c1] = s4.y;
        if (c2 >= 0 && c2 < BKT) g_csrS[(size_t)d4.z * BKT + c2] = s4.z;
        if (c3 >= 0 && c3 < BKT) g_csrS[(size_t)d4.w * BKT + c3] = s4.w;
    }
}

__global__ void k_dinv() {
    int i = blockIdx.x * blockDim.x + threadIdx.x;
    if (i < NN) {
        int d = g_cnt[i];
        g_dinv[i] = (d > 0) ? rsqrtf((float)d) : 0.0f;
    }
}

// ---------------- packed f32x2 helpers -------------------------------------
__device__ __forceinline__ uint64_t packf2(float x, float y) {
    uint64_t r;
    asm("mov.b64 %0, {%1,%2};" : "=l"(r) : "f"(x), "f"(y));
    return r;
}
__device__ __forceinline__ void ffma2(uint64_t& a, uint64_t v, uint64_t w) {
    asm("fma.rn.f32x2 %0, %1, %2, %0;" : "+l"(a) : "l"(v), "l"(w));
}

// acc: 4 packed f32x2 accumulators; p: 8 fp16 values; wp: packed {w,w}
__device__ __forceinline__ void acc8p(uint64_t* A, uint4 p, uint64_t wp) {
    float2 f0 = __half22float2(((const __half2*)&p)[0]);
    float2 f1 = __half22float2(((const __half2*)&p)[1]);
    float2 f2 = __half22float2(((const __half2*)&p)[2]);
    float2 f3 = __half22float2(((const __half2*)&p)[3]);
    ffma2(A[0], packf2(f0.x, f0.y), wp);
    ffma2(A[1], packf2(f1.x, f1.y), wp);
    ffma2(A[2], packf2(f2.x, f2.y), wp);
    ffma2(A[3], packf2(f3.x, f3.y), wp);
}

// ---------------- sparse propagation: fp16 gather, f32x2 accum -------------
// One warp per dst node. Quarter-warp (8 lanes) per edge; lane covers 8
// channels (16B of the 128B fp16 row). Quarter q owns edge slots
// [j+4q, j+4q+4) in the 16-edge main loop -> int4 index loads.
// Weights on the fly: w = -dinv[src]*dinv[dst].
// MODE 0: src=g_xh,  o=g_T1h          MODE 1: src=g_T1h, o=g_T2h, sub=g_xh
// MODE 2: src=g_Yh (norm fused), o=g_T1h
// MODE 3: src=g_T1h, o=g_T2h, sub=norm(g_Yh)
template <int MODE>
__global__ void __launch_bounds__(256, 6) k_prop() {
    const __half* hs;
    __half* o;
    if (MODE == 0) { hs = g_xh;  o = g_T1h; }
    if (MODE == 1) { hs = g_T1h; o = g_T2h; }
    if (MODE == 2) { hs = g_Yh;  o = g_T1h; }
    if (MODE == 3) { hs = g_T1h; o = g_T2h; }

    int node = blockIdx.x * (blockDim.x >> 5) + (threadIdx.x >> 5);
    if (node >= NN) return;
    int lane = threadIdx.x & 31;
    int qtr = lane >> 3;            // 0..3
    int c8 = (lane & 7) * 8;        // channel group (8 ch = 16B fp16)
    int dg = g_cnt[node];
    if (dg > BKT) dg = BKT;
    float ndinv = -g_dinv[node];    // -dinv[dst]
    int beg = node * BKT, end = beg + dg;
    const __half* hc8 = hs + c8;

    uint64_t A[4];
    A[0] = A[1] = A[2] = A[3] = packf2(0.f, 0.f);
    float wsum = 0.f;
    int j = beg;
    // main: 16 edges/warp-iter, quarter q owns slots j+4q..j+4q+3 (int4 idx)
    for (; j + 15 < end; j += 16) {
        int4 s = *(const int4*)&g_csrS[j + qtr * 4];
        uint4 p0 = *(const uint4*)(hc8 + (size_t)s.x * NCH);
        uint4 p1 = *(const uint4*)(hc8 + (size_t)s.y * NCH);
        uint4 p2 = *(const uint4*)(hc8 + (size_t)s.z * NCH);
        uint4 p3 = *(const uint4*)(hc8 + (size_t)s.w * NCH);
        float w0 = ndinv * g_dinv[s.x];
        float w1 = ndinv * g_dinv[s.y];
        float w2 = ndinv * g_dinv[s.z];
        float w3 = ndinv * g_dinv[s.w];
        acc8p(A, p0, packf2(w0, w0));
        acc8p(A, p1, packf2(w1, w1));
        acc8p(A, p2, packf2(w2, w2));
        acc8p(A, p3, packf2(w3, w3));
        if (MODE == 2) wsum += w0 + w1 + w2 + w3;
    }
    // 8 edges/iter: quarter q owns slots j+2q, j+2q+1 (int2 idx)
    for (; j + 7 < end; j += 8) {
        int2 s = *(const int2*)&g_csrS[j + qtr * 2];
        uint4 p0 = *(const uint4*)(hc8 + (size_t)s.x * NCH);
        uint4 p1 = *(const uint4*)(hc8 + (size_t)s.y * NCH);
        float w0 = ndinv * g_dinv[s.x];
        float w1 = ndinv * g_dinv[s.y];
        acc8p(A, p0, packf2(w0, w0));
        acc8p(A, p1, packf2(w1, w1));
        if (MODE == 2) wsum += w0 + w1;
    }
    // tail: 4 edges/iter, predicated
    for (; j < end; j += 4) {
        int jj = j + qtr;
        int s = 0; float w = 0.f;
        if (jj < end) { s = g_csrS[jj]; w = ndinv * g_dinv[s]; }
        uint4 p = *(const uint4*)(hc8 + (size_t)s * NCH);
        acc8p(A, p, packf2(w, w));
        if (MODE == 2) wsum += w;
    }
    // unpack accumulators
    float a[8];
    asm("mov.b64 {%0,%1}, %2;" : "=f"(a[0]), "=f"(a[1]) : "l"(A[0]));
    asm("mov.b64 {%0,%1}, %2;" : "=f"(a[2]), "=f"(a[3]) : "l"(A[1]));
    asm("mov.b64 {%0,%1}, %2;" : "=f"(a[4]), "=f"(a[5]) : "l"(A[2]));
    asm("mov.b64 {%0,%1}, %2;" : "=f"(a[6]), "=f"(a[7]) : "l"(A[3]));
#pragma unroll
    for (int i = 0; i < 8; i++) {
        a[i] += __shfl_xor_sync(0xffffffffu, a[i], 8);
        a[i] += __shfl_xor_sync(0xffffffffu, a[i], 16);
    }
    if (MODE == 2) {
        wsum += __shfl_xor_sync(0xffffffffu, wsum, 8);
        wsum += __shfl_xor_sync(0xffffffffu, wsum, 16);
    }

    if (lane < 8) {
        float r[8];
        if (MODE == 0) {
#pragma unroll
            for (int i = 0; i < 8; i++) r[i] = a[i];
        } else if (MODE == 2) {
            float4 mA = *(const float4*)(g_stats + c8);
            float4 mB = *(const float4*)(g_stats + c8 + 4);
            float4 rA = *(const float4*)(g_stats + 64 + c8);
            float4 rB = *(const float4*)(g_stats + 64 + c8 + 4);
            r[0] = rA.x * a[0] - mA.x * rA.x * wsum;
            r[1] = rA.y * a[1] - mA.y * rA.y * wsum;
            r[2] = rA.z * a[2] - mA.z * rA.z * wsum;
            r[3] = rA.w * a[3] - mA.w * rA.w * wsum;
            r[4] = rB.x * a[4] - mB.x * rB.x * wsum;
            r[5] = rB.y * a[5] - mB.y * rB.y * wsum;
            r[6] = rB.z * a[6] - mB.z * rB.z * wsum;
            r[7] = rB.w * a[7] - mB.w * rB.w * wsum;
        } else {
            uint4 su = *(const uint4*)(((MODE == 1) ? g_xh : g_Yh) +
                                       (size_t)node * NCH + c8);
            float2 s0 = __half22float2(((const __half2*)&su)[0]);
            float2 s1 = __half22float2(((const __half2*)&su)[1]);
            float2 s2 = __half22float2(((const __half2*)&su)[2]);
            float2 s3 = __half22float2(((const __half2*)&su)[3]);
            float sv[8] = {s0.x, s0.y, s1.x, s1.y, s2.x, s2.y, s3.x, s3.y};
            if (MODE == 3) {                   // normalize sub
#pragma unroll
                for (int i = 0; i < 8; i++)
                    sv[i] = (sv[i] - g_stats[c8 + i]) * g_stats[64 + c8 + i];
            }
#pragma unroll
            for (int i = 0; i < 8; i++) r[i] = 2.f * a[i] - sv[i];
        }
        uint4 u;
        ((__half2*)&u)[0] = __floats2half2_rn(r[0], r[1]);
        ((__half2*)&u)[1] = __floats2half2_rn(r[2], r[3]);
        ((__half2*)&u)[2] = __floats2half2_rn(r[4], r[5]);
        ((__half2*)&u)[3] = __floats2half2_rn(r[6], r[7]);
        *(uint4*)(o + (size_t)node * NCH + c8) = u;
    }
}

// ---------------- tf32 helpers ---------------------------------------------
__device__ __forceinline__ uint32_t f2tf(float x) {
    uint32_t r;
    asm("cvt.rna.tf32.f32 %0, %1;" : "=r"(r) : "f"(x));
    return r;
}

__device__ __forceinline__ void mma_tf32(float* c, uint32_t a0, uint32_t a1,
                                         uint32_t a2, uint32_t a3,
                                         uint32_t b0, uint32_t b1) {
    asm volatile(
        "mma.sync.aligned.m16n8k8.row.col.f32.tf32.tf32.f32 "
        "{%0,%1,%2,%3}, {%4,%5,%6,%7}, {%8,%9}, {%0,%1,%2,%3};"
        : "+f"(c[0]), "+f"(c[1]), "+f"(c[2]), "+f"(c[3])
        : "r"(a0), "r"(a1), "r"(a2), "r"(a3), "r"(b0), "r"(b1));
}

// ---------------- ChebConv GEMM (tf32) + fused relu-stats ------------------
// Y = relu([A0|Tx1|Tx2] @ W + b). Block: 128 nodes x 64 cols, K=192 (6x32).
// term0 from fp32 (x or normalized g_Y); terms 1/2 from fp16 shadows.
// LAYER 0 also writes g_Yh.
#define A_P 36
#define B_P 72
template <int LAYER>
__global__ void __launch_bounds__(256)
k_gemm(const float* __restrict__ xp, const float* __restrict__ W,
       const float* __restrict__ bias) {
    __shared__ uint32_t sA[128 * A_P];     // 18432 B
    __shared__ uint32_t sB[32 * B_P];      //  9216 B

    int t = threadIdx.x;
    int lane = t & 31, wm = t >> 5;
    int gid = lane >> 2, tig = lane & 3;
    int nbase = blockIdx.x * 128;

    float acc[8][4];
#pragma unroll
    for (int nt = 0; nt < 8; nt++) {
        float b0 = __ldg(&bias[nt * 8 + 2 * tig]);
        float b1 = __ldg(&bias[nt * 8 + 2 * tig + 1]);
        acc[nt][0] = b0; acc[nt][1] = b1; acc[nt][2] = b0; acc[nt][3] = b1;
    }

#pragma unroll 1
    for (int chunk = 0; chunk < 6; chunk++) {
        int term = chunk >> 1;
        int ch0 = (chunk & 1) * 32;

        if (term == 0) {
            const float* A = (LAYER == 0) ? xp : g_Y;
#pragma unroll
            for (int i = t; i < 1024; i += 256) {
                int nn = i >> 3, q = i & 7;
                int node = nbase + nn;
                float4 v = make_float4(0.f, 0.f, 0.f, 0.f);
                if (node < NN)
                    v = *(const float4*)&A[(size_t)node * NCH + ch0 + q * 4];
                if (LAYER == 1) {
                    float4 m4 = *(const float4*)&g_stats[ch0 + q * 4];
                    float4 r4 = *(const float4*)&g_stats[64 + ch0 + q * 4];
                    v.x = (v.x - m4.x) * r4.x; v.y = (v.y - m4.y) * r4.y;
                    v.z = (v.z - m4.z) * r4.z; v.w = (v.w - m4.w) * r4.w;
                }
                uint32_t* p = &sA[nn * A_P + q * 4];
                p[0] = f2tf(v.x); p[1] = f2tf(v.y);
                p[2] = f2tf(v.z); p[3] = f2tf(v.w);
            }
        } else {
            const __half* A = (term == 1) ? g_T1h : g_T2h;
#pragma unroll
            for (int i = t; i < 512; i += 256) {
                int nn = i >> 2, q = i & 3;       // q covers 8 channels
                int node = nbase + nn;
                uint4 u = make_uint4(0, 0, 0, 0);
                if (node < NN)
                    u = *(const uint4*)(A + (size_t)node * NCH + ch0 + q * 8);
                float2 f0 = __half22float2(((const __half2*)&u)[0]);
                float2 f1 = __half22float2(((const __half2*)&u)[1]);
                float2 f2 = __half22float2(((const __half2*)&u)[2]);
                float2 f3 = __half22float2(((const __half2*)&u)[3]);
                uint32_t* p = &sA[nn * A_P + q * 8];
                p[0] = f2tf(f0.x); p[1] = f2tf(f0.y);
                p[2] = f2tf(f1.x); p[3] = f2tf(f1.y);
                p[4] = f2tf(f2.x); p[5] = f2tf(f2.y);
                p[6] = f2tf(f3.x); p[7] = f2tf(f3.y);
            }
        }
#pragma unroll
        for (int i = t; i < 512; i += 256) {
            int r = i >> 4, qc = (i & 15) * 4;
            float4 v = *(const float4*)&W[(chunk * 32 + r) * 64 + qc];
            uint32_t* p = &sB[r * B_P + qc];
            p[0] = f2tf(v.x); p[1] = f2tf(v.y);
            p[2] = f2tf(v.z); p[3] = f2tf(v.w);
        }
        __syncthreads();

#pragma unroll
        for (int ks = 0; ks < 4; ks++) {
            int k0 = ks * 8;
            int row0 = wm * 16 + gid;
            uint32_t a0 = sA[row0 * A_P + k0 + tig];
            uint32_t a1 = sA[(row0 + 8) * A_P + k0 + tig];
            uint32_t a2 = sA[row0 * A_P + k0 + tig + 4];
            uint32_t a3 = sA[(row0 + 8) * A_P + k0 + tig + 4];
#pragma unroll
            for (int nt = 0; nt < 8; nt++) {
                uint32_t b0 = sB[(k0 + tig) * B_P + nt * 8 + gid];
                uint32_t b1 = sB[(k0 + tig + 4) * B_P + nt * 8 + gid];
                mma_tf32(acc[nt], a0, a1, a2, a3, b0, b1);
            }
        }
        __syncthreads();
    }

    // relu + writeback (+fp16 shadow for layer 0) + per-nt stats reduction
    int nr0 = nbase + wm * 16 + gid;
    int nr1 = nr0 + 8;
    bool ok0 = nr0 < NN, ok1 = nr1 < NN;
    float* ws = (float*)sB;        // 512 floats
    float* wq = ws + 512;          // 512 floats
#pragma unroll
    for (int nt = 0; nt < 8; nt++) {
        int col = nt * 8 + 2 * tig;
        float a = ok0 ? fmaxf(acc[nt][0], 0.f) : 0.f;
        float b = ok0 ? fmaxf(acc[nt][1], 0.f) : 0.f;
        float c = ok1 ? fmaxf(acc[nt][2], 0.f) : 0.f;
        float d = ok1 ? fmaxf(acc[nt][3], 0.f) : 0.f;
        if (ok0) *(float2*)&g_Y[(size_t)nr0 * NCH + col] = make_float2(a, b);
        if (ok1) *(float2*)&g_Y[(size_t)nr1 * NCH + col] = make_float2(c, d);
        if (LAYER == 0) {
            if (ok0) *(__half2*)&g_Yh[(size_t)nr0 * NCH + col] =
                         __floats2half2_rn(a, b);
            if (ok1) *(__half2*)&g_Yh[(size_t)nr1 * NCH + col] =
                         __floats2half2_rn(c, d);
        }
        float s0 = a + c, s1 = b + d;
        float q0 = a * a + c * c, q1 = b * b + d * d;
#pragma unroll
        for (int m = 4; m <= 16; m <<= 1) {
            s0 += __shfl_xor_sync(0xffffffffu, s0, m);
            s1 += __shfl_xor_sync(0xffffffffu, s1, m);
            q0 += __shfl_xor_sync(0xffffffffu, q0, m);
            q1 += __shfl_xor_sync(0xffffffffu, q1, m);
        }
        if (gid == 0) {
            ws[wm * 64 + col]     = s0;
            ws[wm * 64 + col + 1] = s1;
            wq[wm * 64 + col]     = q0;
            wq[wm * 64 + col + 1] = q1;
        }
    }
    __syncthreads();
    if (t < 64) {
        float S = 0.f, Q = 0.f;
#pragma unroll
        for (int w = 0; w < 8; w++) { S += ws[w * 64 + t]; Q += wq[w * 64 + t]; }
        g_part[blockIdx.x * 64 + t] = S;
        g_part[(GB + blockIdx.x) * 64 + t] = Q;
    }
}

// ---------------- stats finalize -------------------------------------------
__global__ void k_stats2() {
    __shared__ float sh[2][1024];
    int c = threadIdx.x & 63, r = threadIdx.x >> 6;   // 16 groups
    float S = 0.f, Q = 0.f;
    for (int b = r; b < GB; b += 16) {
        S += g_part[b * 64 + c];
        Q += g_part[(GB + b) * 64 + c];
    }
    sh[0][threadIdx.x] = S;
    sh[1][threadIdx.x] = Q;
    __syncthreads();
    if (threadIdx.x < 64) {
        float Sf = 0.f, Qf = 0.f;
#pragma unroll
        for (int g = 0; g < 16; g++) {
            Sf += sh[0][g * 64 + c];
            Qf += sh[1][g * 64 + c];
        }
        float m = Sf / (float)NN;
        float var = Qf / (float)NN - m * m;
        g_stats[c] = m;
        g_stats[64 + c] = rsqrtf(var + EPS);
    }
}

// final output norm (layer 2 only)
__global__ void k_norm(float* __restrict__ outp) {
    __shared__ float sm_m[64], sm_r[64];
    if (threadIdx.x < 64) {
        sm_m[threadIdx.x] = g_stats[threadIdx.x];
        sm_r[threadIdx.x] = g_stats[64 + threadIdx.x];
    }
    __syncthreads();
    int i = blockIdx.x * blockDim.x + threadIdx.x;
    int total = NN * (NCH / 4);
    if (i < total) {
        float4 v = ((const float4*)g_Y)[i];
        int q = (i & 15) * 4;
        float4 o;
        o.x = (v.x - sm_m[q + 0]) * sm_r[q + 0];
        o.y = (v.y - sm_m[q + 1]) * sm_r[q + 1];
        o.z = (v.z - sm_m[q + 2]) * sm_r[q + 2];
        o.w = (v.w - sm_m[q + 3]) * sm_r[q + 3];
        ((float4*)outp)[i] = o;
    }
}

// ---------------- launch (kernel launches ONLY — no other CUDA APIs) -------
extern "C" void kernel_launch(void* const* d_in, const int* in_sizes, int n_in,
                              void* d_out, int out_size) {
    const float* x        = (const float*)d_in[0];
    const int* ei         = (const int*)d_in[1];
    const float* W1       = (const float*)d_in[2];
    const float* b1       = (const float*)d_in[3];
    const float* W2       = (const float*)d_in[4];
    const float* b2       = (const float*)d_in[5];
    float* out            = (float*)d_out;

    const int TB = 256;
    int nodeBlocks = (NN + TB - 1) / TB;
    int initBlocks = (NN * NCH / 8 + TB - 1) / TB;
    int edge4Blocks = (NE / 4 + TB - 1) / TB;
    int propBlocks = (NN + 7) / 8;
    int normBlocks = (NN * 16 + TB - 1) / TB;

    // ----- build: counters + fp16 shadow, bucket fill (counts deg), dinv ---
    k_init<<<initBlocks, TB>>>(x);
    k_fill<<<edge4Blocks, TB>>>(ei);
    k_dinv<<<nodeBlocks, TB>>>();

    // ----- layer 1 -----
    k_prop<0><<<propBlocks, TB>>>();
    k_prop<1><<<propBlocks, TB>>>();
    k_gemm<0><<<GB, 256>>>(x, W1, b1);
    k_stats2<<<1, 1024>>>();

    // ----- layer 2 (H never materialized; norm fused into consumers) -----
    k_prop<2><<<propBlocks, TB>>>();
    k_prop<3><<<propBlocks, TB>>>();
    k_gemm<1><<<GB, 256>>>(x, W2, b2);
    k_stats2<<<1, 1024>>>();
    k_norm<<<normBlocks, TB>>>(out);
}

// round 15
// speedup vs baseline: 1.0569x; 1.0569x over previous
#include <cuda_runtime.h>
#include <cuda_fp16.h>
#include <cstdint>

#define NN 100000
#define NE 1600000
#define NCH 64
#define EPS 1e-5f
#define BKT 64                                 // bucket capacity per node
#define GB  ((NN + 127) / 128)                 // 782 gemm blocks

// ---------------- scratch (device globals; no allocation allowed) ----------
__device__ int    g_cnt[NN];
__device__ float  g_dinv[NN];
__device__ int    g_csrS[(size_t)NN * BKT];    // padded buckets: src only
__device__ float  g_Y[(size_t)NN * NCH];
__device__ __half g_xh[(size_t)NN * NCH];      // fp16 shadow of x
__device__ __half g_T1h[(size_t)NN * NCH];     // fp16 Tx1 (per layer)
__device__ __half g_T2h[(size_t)NN * NCH];     // fp16 Tx2 (per layer)
__device__ __half g_Yh[(size_t)NN * NCH];      // fp16 relu(Y) layer1
__device__ float  g_part[2 * GB * NCH];
__device__ float  g_stats[2 * NCH];

// ---------------- init: zero counters + fp16 shadow of x -------------------
__global__ void k_init(const float* __restrict__ x) {
    int i = blockIdx.x * blockDim.x + threadIdx.x;
    if (i < NN) g_cnt[i] = 0;
    if (i < NN * NCH / 8) {
        float4 a = ((const float4*)x)[2 * i];
        float4 b = ((const float4*)x)[2 * i + 1];
        uint4 u;
        ((__half2*)&u)[0] = __floats2half2_rn(a.x, a.y);
        ((__half2*)&u)[1] = __floats2half2_rn(a.z, a.w);
        ((__half2*)&u)[2] = __floats2half2_rn(b.x, b.y);
        ((__half2*)&u)[3] = __floats2half2_rn(b.z, b.w);
        ((uint4*)g_xh)[i] = u;
    }
}

// ---------------- bucket fill: count + store src, 4 edges/thread -----------
// edge_index is int32 (JAX default x64-disabled demotes int64 -> int32)
__global__ void k_fill(const int* __restrict__ ei) {
    int i = blockIdx.x * blockDim.x + threadIdx.x;
    if (i < NE / 4) {
        int4 s4 = ((const int4*)ei)[i];
        int4 d4 = ((const int4*)(ei + NE))[i];
        int c0 = -1, c1 = -1, c2 = -1, c3 = -1;
        if ((unsigned)s4.x < NN && (unsigned)d4.x < NN)
            c0 = atomicAdd(&g_cnt[d4.x], 1);
        if ((unsigned)s4.y < NN && (unsigned)d4.y < NN)
            c1 = atomicAdd(&g_cnt[d4.y], 1);
        if ((unsigned)s4.z < NN && (unsigned)d4.z < NN)
            c2 = atomicAdd(&g_cnt[d4.z], 1);
        if ((unsigned)s4.w < NN && (unsigned)d4.w < NN)
            c3 = atomicAdd(&g_cnt[d4.w], 1);
        if (c0 >= 0 && c0 < BKT) g_csrS[(size_t)d4.x * BKT + c0] = s4.x;
        if (c1 >= 0 && c1 < BKT) g_csrS[(size_t)d4.y * BKT + c1] = s4.y;
        if (c2 >= 0 && c2 < BKT) g_csrS[(size_t)d4.z * BKT + c2] = s4.z;
        if (c3 >= 0 && c3 < BKT) g_csrS[(size_t)d4.w * BKT + c3] = s4.w;
    }
}

__global__ void k_dinv() {
    int i = blockIdx.x * blockDim.x + threadIdx.x;
    if (i < NN) {
        int d = g_cnt[i];
        g_dinv[i] = (d > 0) ? rsqrtf((float)d) : 0.0f;
    }
}

// ---------------- sparse propagation: fp16 gather, fp32 accum --------------
// 8 warps/block; each warp handles ~4 nodes via grid-stride (halves
// block-retire imbalance from Poisson(16) degrees).
// Quarter-warp (8 lanes) per edge; lane covers 8 channels (16B of the 128B
// fp16 row). 16-edge main loop: quarter q owns slots j+4q..+3 (int4 idx).
// Weights on the fly: w = -dinv[src]*dinv[dst].
// MODE 0: src=g_xh,  o=g_T1h          MODE 1: src=g_T1h, o=g_T2h, sub=g_xh
// MODE 2: src=g_Yh (norm fused), o=g_T1h
// MODE 3: src=g_T1h, o=g_T2h, sub=norm(g_Yh)
__device__ __forceinline__ void acc8(float* a, uint4 p, float w) {
    float2 f0 = __half22float2(((const __half2*)&p)[0]);
    float2 f1 = __half22float2(((const __half2*)&p)[1]);
    float2 f2 = __half22float2(((const __half2*)&p)[2]);
    float2 f3 = __half22float2(((const __half2*)&p)[3]);
    a[0] += w * f0.x; a[1] += w * f0.y;
    a[2] += w * f1.x; a[3] += w * f1.y;
    a[4] += w * f2.x; a[5] += w * f2.y;
    a[6] += w * f3.x; a[7] += w * f3.y;
}

template <int MODE>
__global__ void __launch_bounds__(256, 6) k_prop() {
    const __half* hs;
    __half* o;
    if (MODE == 0) { hs = g_xh;  o = g_T1h; }
    if (MODE == 1) { hs = g_T1h; o = g_T2h; }
    if (MODE == 2) { hs = g_Yh;  o = g_T1h; }
    if (MODE == 3) { hs = g_T1h; o = g_T2h; }

    int warpsTotal = gridDim.x * (blockDim.x >> 5);
    int warpId = blockIdx.x * (blockDim.x >> 5) + (threadIdx.x >> 5);
    int lane = threadIdx.x & 31;
    int qtr = lane >> 3;            // 0..3
    int c8 = (lane & 7) * 8;        // channel group (8 ch = 16B fp16)
    const __half* hc8 = hs + c8;

    for (int node = warpId; node < NN; node += warpsTotal) {
        int dg = g_cnt[node];
        if (dg > BKT) dg = BKT;
        float ndinv = -g_dinv[node];    // -dinv[dst]
        int beg = node * BKT, end = beg + dg;

        float a[8] = {0.f, 0.f, 0.f, 0.f, 0.f, 0.f, 0.f, 0.f};
        float wsum = 0.f;
        int j = beg;
        // main: 16 edges/warp-iter, quarter q owns slots j+4q..+3
        for (; j + 15 < end; j += 16) {
            int4 s = *(const int4*)&g_csrS[j + qtr * 4];
            uint4 p0 = *(const uint4*)(hc8 + (size_t)s.x * NCH);
            uint4 p1 = *(const uint4*)(hc8 + (size_t)s.y * NCH);
            uint4 p2 = *(const uint4*)(hc8 + (size_t)s.z * NCH);
            uint4 p3 = *(const uint4*)(hc8 + (size_t)s.w * NCH);
            float w0 = ndinv * g_dinv[s.x];
            float w1 = ndinv * g_dinv[s.y];
            float w2 = ndinv * g_dinv[s.z];
            float w3 = ndinv * g_dinv[s.w];
            acc8(a, p0, w0);
            acc8(a, p1, w1);
            acc8(a, p2, w2);
            acc8(a, p3, w3);
            if (MODE == 2) wsum += w0 + w1 + w2 + w3;
        }
        // 8 edges/iter: quarter q owns slots j+2q, j+2q+1
        for (; j + 7 < end; j += 8) {
            int2 s = *(const int2*)&g_csrS[j + qtr * 2];
            uint4 p0 = *(const uint4*)(hc8 + (size_t)s.x * NCH);
            uint4 p1 = *(const uint4*)(hc8 + (size_t)s.y * NCH);
            float w0 = ndinv * g_dinv[s.x];
            float w1 = ndinv * g_dinv[s.y];
            acc8(a, p0, w0);
            acc8(a, p1, w1);
            if (MODE == 2) wsum += w0 + w1;
        }
        // tail: 4 edges/iter, predicated
        for (; j < end; j += 4) {
            int jj = j + qtr;
            int s = 0; float w = 0.f;
            if (jj < end) { s = g_csrS[jj]; w = ndinv * g_dinv[s]; }
            uint4 p = *(const uint4*)(hc8 + (size_t)s * NCH);
            acc8(a, p, w);
            if (MODE == 2) wsum += w;
        }
#pragma unroll
        for (int i = 0; i < 8; i++) {
            a[i] += __shfl_xor_sync(0xffffffffu, a[i], 8);
            a[i] += __shfl_xor_sync(0xffffffffu, a[i], 16);
        }
        if (MODE == 2) {
            wsum += __shfl_xor_sync(0xffffffffu, wsum, 8);
            wsum += __shfl_xor_sync(0xffffffffu, wsum, 16);
        }

        if (lane < 8) {
            float r[8];
            if (MODE == 0) {
#pragma unroll
                for (int i = 0; i < 8; i++) r[i] = a[i];
            } else if (MODE == 2) {
                float4 mA = *(const float4*)(g_stats + c8);
                float4 mB = *(const float4*)(g_stats + c8 + 4);
                float4 rA = *(const float4*)(g_stats + 64 + c8);
                float4 rB = *(const float4*)(g_stats + 64 + c8 + 4);
                r[0] = rA.x * a[0] - mA.x * rA.x * wsum;
                r[1] = rA.y * a[1] - mA.y * rA.y * wsum;
                r[2] = rA.z * a[2] - mA.z * rA.z * wsum;
                r[3] = rA.w * a[3] - mA.w * rA.w * wsum;
                r[4] = rB.x * a[4] - mB.x * rB.x * wsum;
                r[5] = rB.y * a[5] - mB.y * rB.y * wsum;
                r[6] = rB.z * a[6] - mB.z * rB.z * wsum;
                r[7] = rB.w * a[7] - mB.w * rB.w * wsum;
            } else {
                uint4 su = *(const uint4*)(((MODE == 1) ? g_xh : g_Yh) +
                                           (size_t)node * NCH + c8);
                float2 s0 = __half22float2(((const __half2*)&su)[0]);
                float2 s1 = __half22float2(((const __half2*)&su)[1]);
                float2 s2 = __half22float2(((const __half2*)&su)[2]);
                float2 s3 = __half22float2(((const __half2*)&su)[3]);
                float sv[8] = {s0.x, s0.y, s1.x, s1.y,
                               s2.x, s2.y, s3.x, s3.y};
                if (MODE == 3) {               // normalize sub
#pragma unroll
                    for (int i = 0; i < 8; i++)
                        sv[i] = (sv[i] - g_stats[c8 + i]) *
                                g_stats[64 + c8 + i];
                }
#pragma unroll
                for (int i = 0; i < 8; i++) r[i] = 2.f * a[i] - sv[i];
            }
            uint4 u;
            ((__half2*)&u)[0] = __floats2half2_rn(r[0], r[1]);
            ((__half2*)&u)[1] = __floats2half2_rn(r[2], r[3]);
            ((__half2*)&u)[2] = __floats2half2_rn(r[4], r[5]);
            ((__half2*)&u)[3] = __floats2half2_rn(r[6], r[7]);
            *(uint4*)(o + (size_t)node * NCH + c8) = u;
        }
    }
}

// ---------------- tf32 helpers ---------------------------------------------
__device__ __forceinline__ uint32_t f2tf(float x) {
    uint32_t r;
    asm("cvt.rna.tf32.f32 %0, %1;" : "=r"(r) : "f"(x));
    return r;
}

__device__ __forceinline__ void mma_tf32(float* c, uint32_t a0, uint32_t a1,
                                         uint32_t a2, uint32_t a3,
                                         uint32_t b0, uint32_t b1) {
    asm volatile(
        "mma.sync.aligned.m16n8k8.row.col.f32.tf32.tf32.f32 "
        "{%0,%1,%2,%3}, {%4,%5,%6,%7}, {%8,%9}, {%0,%1,%2,%3};"
        : "+f"(c[0]), "+f"(c[1]), "+f"(c[2]), "+f"(c[3])
        : "r"(a0), "r"(a1), "r"(a2), "r"(a3), "r"(b0), "r"(b1));
}

// ---------------- ChebConv GEMM (tf32) + fused relu-stats ------------------
// Y = relu([A0|Tx1|Tx2] @ W + b). Block: 128 nodes x 64 cols, K=192 (6x32).
// term0 from fp32 (x or normalized g_Y); terms 1/2 from fp16 shadows.
// LAYER 0 also writes g_Yh.
#define A_P 36
#define B_P 72
template <int LAYER>
__global__ void __launch_bounds__(256)
k_gemm(const float* __restrict__ xp, const float* __restrict__ W,
       const float* __restrict__ bias) {
    __shared__ uint32_t sA[128 * A_P];     // 18432 B
    __shared__ uint32_t sB[32 * B_P];      //  9216 B

    int t = threadIdx.x;
    int lane = t & 31, wm = t >> 5;
    int gid = lane >> 2, tig = lane & 3;
    int nbase = blockIdx.x * 128;

    float acc[8][4];
#pragma unroll
    for (int nt = 0; nt < 8; nt++) {
        float b0 = __ldg(&bias[nt * 8 + 2 * tig]);
        float b1 = __ldg(&bias[nt * 8 + 2 * tig + 1]);
        acc[nt][0] = b0; acc[nt][1] = b1; acc[nt][2] = b0; acc[nt][3] = b1;
    }

#pragma unroll 1
    for (int chunk = 0; chunk < 6; chunk++) {
        int term = chunk >> 1;
        int ch0 = (chunk & 1) * 32;

        if (term == 0) {
            const float* A = (LAYER == 0) ? xp : g_Y;
#pragma unroll
            for (int i = t; i < 1024; i += 256) {
                int nn = i >> 3, q = i & 7;
                int node = nbase + nn;
                float4 v = make_float4(0.f, 0.f, 0.f, 0.f);
                if (node < NN)
                    v = *(const float4*)&A[(size_t)node * NCH + ch0 + q * 4];
                if (LAYER == 1) {
                    float4 m4 = *(const float4*)&g_stats[ch0 + q * 4];
                    float4 r4 = *(const float4*)&g_stats[64 + ch0 + q * 4];
                    v.x = (v.x - m4.x) * r4.x; v.y = (v.y - m4.y) * r4.y;
                    v.z = (v.z - m4.z) * r4.z; v.w = (v.w - m4.w) * r4.w;
                }
                uint32_t* p = &sA[nn * A_P + q * 4];
                p[0] = f2tf(v.x); p[1] = f2tf(v.y);
                p[2] = f2tf(v.z); p[3] = f2tf(v.w);
            }
        } else {
            const __half* A = (term == 1) ? g_T1h : g_T2h;
#pragma unroll
            for (int i = t; i < 512; i += 256) {
                int nn = i >> 2, q = i & 3;       // q covers 8 channels
                int node = nbase + nn;
                uint4 u = make_uint4(0, 0, 0, 0);
                if (node < NN)
                    u = *(const uint4*)(A + (size_t)node * NCH + ch0 + q * 8);
                float2 f0 = __half22float2(((const __half2*)&u)[0]);
                float2 f1 = __half22float2(((const __half2*)&u)[1]);
                float2 f2 = __half22float2(((const __half2*)&u)[2]);
                float2 f3 = __half22float2(((const __half2*)&u)[3]);
                uint32_t* p = &sA[nn * A_P + q * 8];
                p[0] = f2tf(f0.x); p[1] = f2tf(f0.y);
                p[2] = f2tf(f1.x); p[3] = f2tf(f1.y);
                p[4] = f2tf(f2.x); p[5] = f2tf(f2.y);
                p[6] = f2tf(f3.x); p[7] = f2tf(f3.y);
            }
        }
#pragma unroll
        for (int i = t; i < 512; i += 256) {
            int r = i >> 4, qc = (i & 15) * 4;
            float4 v = *(const float4*)&W[(chunk * 32 + r) * 64 + qc];
            uint32_t* p = &sB[r * B_P + qc];
            p[0] = f2tf(v.x); p[1] = f2tf(v.y);
            p[2] = f2tf(v.z); p[3] = f2tf(v.w);
        }
        __syncthreads();

#pragma unroll
        for (int ks = 0; ks < 4; ks++) {
            int k0 = ks * 8;
            int row0 = wm * 16 + gid;
            uint32_t a0 = sA[row0 * A_P + k0 + tig];
            uint32_t a1 = sA[(row0 + 8) * A_P + k0 + tig];
            uint32_t a2 = sA[row0 * A_P + k0 + tig + 4];
            uint32_t a3 = sA[(row0 + 8) * A_P + k0 + tig + 4];
#pragma unroll
            for (int nt = 0; nt < 8; nt++) {
                uint32_t b0 = sB[(k0 + tig) * B_P + nt * 8 + gid];
                uint32_t b1 = sB[(k0 + tig + 4) * B_P + nt * 8 + gid];
                mma_tf32(acc[nt], a0, a1, a2, a3, b0, b1);
            }
        }
        __syncthreads();
    }

    // relu + writeback (+fp16 shadow for layer 0) + per-nt stats reduction
    int nr0 = nbase + wm * 16 + gid;
    int nr1 = nr0 + 8;
    bool ok0 = nr0 < NN, ok1 = nr1 < NN;
    float* ws = (float*)sB;        // 512 floats
    float* wq = ws + 512;          // 512 floats
#pragma unroll
    for (int nt = 0; nt < 8; nt++) {
        int col = nt * 8 + 2 * tig;
        float a = ok0 ? fmaxf(acc[nt][0], 0.f) : 0.f;
        float b = ok0 ? fmaxf(acc[nt][1], 0.f) : 0.f;
        float c = ok1 ? fmaxf(acc[nt][2], 0.f) : 0.f;
        float d = ok1 ? fmaxf(acc[nt][3], 0.f) : 0.f;
        if (ok0) *(float2*)&g_Y[(size_t)nr0 * NCH + col] = make_float2(a, b);
        if (ok1) *(float2*)&g_Y[(size_t)nr1 * NCH + col] = make_float2(c, d);
        if (LAYER == 0) {
            if (ok0) *(__half2*)&g_Yh[(size_t)nr0 * NCH + col] =
                         __floats2half2_rn(a, b);
            if (ok1) *(__half2*)&g_Yh[(size_t)nr1 * NCH + col] =
                         __floats2half2_rn(c, d);
        }
        float s0 = a + c, s1 = b + d;
        float q0 = a * a + c * c, q1 = b * b + d * d;
#pragma unroll
        for (int m = 4; m <= 16; m <<= 1) {
            s0 += __shfl_xor_sync(0xffffffffu, s0, m);
            s1 += __shfl_xor_sync(0xffffffffu, s1, m);
            q0 += __shfl_xor_sync(0xffffffffu, q0, m);
            q1 += __shfl_xor_sync(0xffffffffu, q1, m);
        }
        if (gid == 0) {
            ws[wm * 64 + col]     = s0;
            ws[wm * 64 + col + 1] = s1;
            wq[wm * 64 + col]     = q0;
            wq[wm * 64 + col + 1] = q1;
        }
    }
    __syncthreads();
    if (t < 64) {
        float S = 0.f, Q = 0.f;
#pragma unroll
        for (int w = 0; w < 8; w++) { S += ws[w * 64 + t]; Q += wq[w * 64 + t]; }
        g_part[blockIdx.x * 64 + t] = S;
        g_part[(GB + blockIdx.x) * 64 + t] = Q;
    }
}

// ---------------- stats finalize -------------------------------------------
__global__ void k_stats2() {
    __shared__ float sh[2][1024];
    int c = threadIdx.x & 63, r = threadIdx.x >> 6;   // 16 groups
    float S = 0.f, Q = 0.f;
    for (int b = r; b < GB; b += 16) {
        S += g_part[b * 64 + c];
        Q += g_part[(GB + b) * 64 + c];
    }
    sh[0][threadIdx.x] = S;
    sh[1][threadIdx.x] = Q;
    __syncthreads();
    if (threadIdx.x < 64) {
        float Sf = 0.f, Qf = 0.f;
#pragma unroll
        for (int g = 0; g < 16; g++) {
            Sf += sh[0][g * 64 + c];
            Qf += sh[1][g * 64 + c];
        }
        float m = Sf / (float)NN;
        float var = Qf / (float)NN - m * m;
        g_stats[c] = m;
        g_stats[64 + c] = rsqrtf(var + EPS);
    }
}

// final output norm (layer 2 only)
__global__ void k_norm(float* __restrict__ outp) {
    __shared__ float sm_m[64], sm_r[64];
    if (threadIdx.x < 64) {
        sm_m[threadIdx.x] = g_stats[threadIdx.x];
        sm_r[threadIdx.x] = g_stats[64 + threadIdx.x];
    }
    __syncthreads();
    int i = blockIdx.x * blockDim.x + threadIdx.x;
    int total = NN * (NCH / 4);
    if (i < total) {
        float4 v = ((const float4*)g_Y)[i];
        int q = (i & 15) * 4;
        float4 o;
        o.x = (v.x - sm_m[q + 0]) * sm_r[q + 0];
        o.y = (v.y - sm_m[q + 1]) * sm_r[q + 1];
        o.z = (v.z - sm_m[q + 2]) * sm_r[q + 2];
        o.w = (v.w - sm_m[q + 3]) * sm_r[q + 3];
        ((float4*)outp)[i] = o;
    }
}

// ---------------- launch (kernel launches ONLY — no other CUDA APIs) -------
extern "C" void kernel_launch(void* const* d_in, const int* in_sizes, int n_in,
                              void* d_out, int out_size) {
    const float* x        = (const float*)d_in[0];
    const int* ei         = (const int*)d_in[1];
    const float* W1       = (const float*)d_in[2];
    const float* b1       = (const float*)d_in[3];
    const float* W2       = (const float*)d_in[4];
    const float* b2       = (const float*)d_in[5];
    float* out            = (float*)d_out;

    const int TB = 256;
    int nodeBlocks = (NN + TB - 1) / TB;
    int initBlocks = (NN * NCH / 8 + TB - 1) / TB;
    int edge4Blocks = (NE / 4 + TB - 1) / TB;
    int propBlocks = (NN / 4 + 7) / 8;        // ~4 nodes per warp
    int normBlocks = (NN * 16 + TB - 1) / TB;

    // ----- build: counters + fp16 shadow, bucket fill (counts deg), dinv ---
    k_init<<<initBlocks, TB>>>(x);
    k_fill<<<edge4Blocks, TB>>>(ei);
    k_dinv<<<nodeBlocks, TB>>>();

    // ----- layer 1 -----
    k_prop<0><<<propBlocks, TB>>>();
    k_prop<1><<<propBlocks, TB>>>();
    k_gemm<0><<<GB, 256>>>(x, W1, b1);
    k_stats2<<<1, 1024>>>();

    // ----- layer 2 (H never materialized; norm fused into consumers) -----
    k_prop<2><<<propBlocks, TB>>>();
    k_prop<3><<<propBlocks, TB>>>();
    k_gemm<1><<<GB, 256>>>(x, W2, b2);
    k_stats2<<<1, 1024>>>();
    k_norm<<<normBlocks, TB>>>(out);
}

// round 16
// speedup vs baseline: 1.0789x; 1.0208x over previous
#include <cuda_runtime.h>
#include <cuda_fp16.h>
#include <cstdint>

#define NN 100000
#define NE 1600000
#define NCH 64
#define EPS 1e-5f
#define BKT 64                                 // bucket capacity per node
#define GB  ((NN + 127) / 128)                 // 782 gemm blocks

// ---------------- scratch (device globals; no allocation allowed) ----------
__device__ int    g_cnt[NN];
__device__ float  g_dinv[NN];
__device__ float  g_sq[NN];                    // sqrt(deg): unscale factor
__device__ float  g_wsum[NN];                  // sum of dinv[src] per node
__device__ int    g_csrS[(size_t)NN * BKT];    // padded buckets: src only
__device__ float  g_Y[(size_t)NN * NCH];
__device__ __half g_xh[(size_t)NN * NCH];      // PRESCALED dinv*x
__device__ __half g_T1h[(size_t)NN * NCH];     // PRESCALED dinv*Tx1
__device__ __half g_T2h[(size_t)NN * NCH];     // unscaled Tx2 (GEMM only)
__device__ __half g_Yh[(size_t)NN * NCH];      // PRESCALED dinv*relu(Y) L1
__device__ float  g_part[2 * GB * NCH];
__device__ float  g_stats[2 * NCH];

// ---------------- zero counters --------------------------------------------
__global__ void k_zero() {
    int i = blockIdx.x * blockDim.x + threadIdx.x;
    if (i < NN) g_cnt[i] = 0;
}

// ---------------- bucket fill: count + store src, 4 edges/thread -----------
// edge_index is int32 (JAX default x64-disabled demotes int64 -> int32)
__global__ void k_fill(const int* __restrict__ ei) {
    int i = blockIdx.x * blockDim.x + threadIdx.x;
    if (i < NE / 4) {
        int4 s4 = ((const int4*)ei)[i];
        int4 d4 = ((const int4*)(ei + NE))[i];
        int c0 = -1, c1 = -1, c2 = -1, c3 = -1;
        if ((unsigned)s4.x < NN && (unsigned)d4.x < NN)
            c0 = atomicAdd(&g_cnt[d4.x], 1);
        if ((unsigned)s4.y < NN && (unsigned)d4.y < NN)
            c1 = atomicAdd(&g_cnt[d4.y], 1);
        if ((unsigned)s4.z < NN && (unsigned)d4.z < NN)
            c2 = atomicAdd(&g_cnt[d4.z], 1);
        if ((unsigned)s4.w < NN && (unsigned)d4.w < NN)
            c3 = atomicAdd(&g_cnt[d4.w], 1);
        if (c0 >= 0 && c0 < BKT) g_csrS[(size_t)d4.x * BKT + c0] = s4.x;
        if (c1 >= 0 && c1 < BKT) g_csrS[(size_t)d4.y * BKT + c1] = s4.y;
        if (c2 >= 0 && c2 < BKT) g_csrS[(size_t)d4.z * BKT + c2] = s4.z;
        if (c3 >= 0 && c3 < BKT) g_csrS[(size_t)d4.w * BKT + c3] = s4.w;
    }
}

__global__ void k_dinv() {
    int i = blockIdx.x * blockDim.x + threadIdx.x;
    if (i < NN) {
        int d = g_cnt[i];
        g_dinv[i] = (d > 0) ? rsqrtf((float)d) : 0.0f;
        g_sq[i]   = (d > 0) ? sqrtf((float)d)  : 0.0f;
    }
}

// xh = dinv[n] * x[n]  (prescaled fp16 shadow)
__global__ void k_scalex(const float* __restrict__ x) {
    int i = blockIdx.x * blockDim.x + threadIdx.x;   // 8 elems/thread
    if (i < NN * NCH / 8) {
        float dv = g_dinv[i >> 3];
        float4 a = ((const float4*)x)[2 * i];
        float4 b = ((const float4*)x)[2 * i + 1];
        uint4 u;
        ((__half2*)&u)[0] = __floats2half2_rn(dv * a.x, dv * a.y);
        ((__half2*)&u)[1] = __floats2half2_rn(dv * a.z, dv * a.w);
        ((__half2*)&u)[2] = __floats2half2_rn(dv * b.x, dv * b.y);
        ((__half2*)&u)[3] = __floats2half2_rn(dv * b.z, dv * b.w);
        ((uint4*)g_xh)[i] = u;
    }
}

// ---------------- sparse propagation: prescaled fp16 gather, pure sums -----
// 8 warps/block; each warp handles ~4 nodes via grid-stride. Quarter-warp
// (8 lanes) per edge; lane covers 8 channels. Inner loop: acc += cvt(p).
// MODE 0: src=g_xh,  out T1h (prescaled); also computes g_wsum
// MODE 1: src=g_T1h, out T2h, sub=xp fp32
// MODE 2: src=g_Yh,  out T1h (prescaled); uses g_wsum + stats
// MODE 3: src=g_T1h, out T2h, sub=(g_Y-m)*rstd fp32
__device__ __forceinline__ void acc8s(float* a, uint4 p) {
    float2 f0 = __half22float2(((const __half2*)&p)[0]);
    float2 f1 = __half22float2(((const __half2*)&p)[1]);
    float2 f2 = __half22float2(((const __half2*)&p)[2]);
    float2 f3 = __half22float2(((const __half2*)&p)[3]);
    a[0] += f0.x; a[1] += f0.y;
    a[2] += f1.x; a[3] += f1.y;
    a[4] += f2.x; a[5] += f2.y;
    a[6] += f3.x; a[7] += f3.y;
}

template <int MODE>
__global__ void __launch_bounds__(256, 6) k_prop(const float* __restrict__ xp) {
    const __half* hs;
    __half* o;
    if (MODE == 0) { hs = g_xh;  o = g_T1h; }
    if (MODE == 1) { hs = g_T1h; o = g_T2h; }
    if (MODE == 2) { hs = g_Yh;  o = g_T1h; }
    if (MODE == 3) { hs = g_T1h; o = g_T2h; }

    int warpsTotal = gridDim.x * (blockDim.x >> 5);
    int warpId = blockIdx.x * (blockDim.x >> 5) + (threadIdx.x >> 5);
    int lane = threadIdx.x & 31;
    int qtr = lane >> 3;            // 0..3
    int c8 = (lane & 7) * 8;        // channel group (8 ch = 16B fp16)
    const __half* hc8 = hs + c8;

    for (int node = warpId; node < NN; node += warpsTotal) {
        int dg = g_cnt[node];
        if (dg > BKT) dg = BKT;
        int beg = node * BKT, end = beg + dg;

        float a[8] = {0.f, 0.f, 0.f, 0.f, 0.f, 0.f, 0.f, 0.f};
        float wsum = 0.f;
        int j = beg;
        for (; j + 15 < end; j += 16) {
            int4 s = *(const int4*)&g_csrS[j + qtr * 4];
            uint4 p0 = *(const uint4*)(hc8 + (size_t)s.x * NCH);
            uint4 p1 = *(const uint4*)(hc8 + (size_t)s.y * NCH);
            uint4 p2 = *(const uint4*)(hc8 + (size_t)s.z * NCH);
            uint4 p3 = *(const uint4*)(hc8 + (size_t)s.w * NCH);
            acc8s(a, p0);
            acc8s(a, p1);
            acc8s(a, p2);
            acc8s(a, p3);
            if (MODE == 0)
                wsum += g_dinv[s.x] + g_dinv[s.y] + g_dinv[s.z] + g_dinv[s.w];
        }
        for (; j + 7 < end; j += 8) {
            int2 s = *(const int2*)&g_csrS[j + qtr * 2];
            uint4 p0 = *(const uint4*)(hc8 + (size_t)s.x * NCH);
            uint4 p1 = *(const uint4*)(hc8 + (size_t)s.y * NCH);
            acc8s(a, p0);
            acc8s(a, p1);
            if (MODE == 0) wsum += g_dinv[s.x] + g_dinv[s.y];
        }
        for (; j < end; j += 4) {               // tail, quarter-uniform pred
            int jj = j + qtr;
            if (jj < end) {
                int s = g_csrS[jj];
                uint4 p = *(const uint4*)(hc8 + (size_t)s * NCH);
                acc8s(a, p);
                if (MODE == 0) wsum += g_dinv[s];
            }
        }
#pragma unroll
        for (int i = 0; i < 8; i++) {
            a[i] += __shfl_xor_sync(0xffffffffu, a[i], 8);
            a[i] += __shfl_xor_sync(0xffffffffu, a[i], 16);
        }
        if (MODE == 0) {
            wsum += __shfl_xor_sync(0xffffffffu, wsum, 8);
            wsum += __shfl_xor_sync(0xffffffffu, wsum, 16);
        }

        if (lane < 8) {
            float dv = g_dinv[node];
            float nd = -dv;
            float r[8];
            if (MODE == 0) {
                if (lane == 0) g_wsum[node] = wsum;
#pragma unroll
                for (int i = 0; i < 8; i++) r[i] = nd * a[i];
                // store prescaled: dv * r
#pragma unroll
                for (int i = 0; i < 8; i++) r[i] *= dv;
            } else if (MODE == 2) {
                float W = g_wsum[node];
                float4 mA = *(const float4*)(g_stats + c8);
                float4 mB = *(const float4*)(g_stats + c8 + 4);
                float4 rA = *(const float4*)(g_stats + 64 + c8);
                float4 rB = *(const float4*)(g_stats + 64 + c8 + 4);
                r[0] = nd * rA.x * (a[0] - mA.x * W);
                r[1] = nd * rA.y * (a[1] - mA.y * W);
                r[2] = nd * rA.z * (a[2] - mA.z * W);
                r[3] = nd * rA.w * (a[3] - mA.w * W);
                r[4] = nd * rB.x * (a[4] - mB.x * W);
                r[5] = nd * rB.y * (a[5] - mB.y * W);
                r[6] = nd * rB.z * (a[6] - mB.z * W);
                r[7] = nd * rB.w * (a[7] - mB.w * W);
#pragma unroll
                for (int i = 0; i < 8; i++) r[i] *= dv;  // prescale for T1h
            } else if (MODE == 1) {
                float4 s0 = *(const float4*)(xp + (size_t)node * NCH + c8);
                float4 s1 = *(const float4*)(xp + (size_t)node * NCH + c8 + 4);
                float t = 2.f * nd;
                r[0] = t * a[0] - s0.x; r[1] = t * a[1] - s0.y;
                r[2] = t * a[2] - s0.z; r[3] = t * a[3] - s0.w;
                r[4] = t * a[4] - s1.x; r[5] = t * a[5] - s1.y;
                r[6] = t * a[6] - s1.z; r[7] = t * a[7] - s1.w;
            } else { // MODE 3
                float4 s0 = *(const float4*)(g_Y + (size_t)node * NCH + c8);
                float4 s1 = *(const float4*)(g_Y + (size_t)node * NCH + c8 + 4);
                float4 mA = *(const float4*)(g_stats + c8);
                float4 mB = *(const float4*)(g_stats + c8 + 4);
                float4 rA = *(const float4*)(g_stats + 64 + c8);
                float4 rB = *(const float4*)(g_stats + 64 + c8 + 4);
                float t = 2.f * nd;
                r[0] = t * a[0] - (s0.x - mA.x) * rA.x;
                r[1] = t * a[1] - (s0.y - mA.y) * rA.y;
                r[2] = t * a[2] - (s0.z - mA.z) * rA.z;
                r[3] = t * a[3] - (s0.w - mA.w) * rA.w;
                r[4] = t * a[4] - (s1.x - mB.x) * rB.x;
                r[5] = t * a[5] - (s1.y - mB.y) * rB.y;
                r[6] = t * a[6] - (s1.z - mB.z) * rB.z;
                r[7] = t * a[7] - (s1.w - mB.w) * rB.w;
            }
            uint4 u;
            ((__half2*)&u)[0] = __floats2half2_rn(r[0], r[1]);
            ((__half2*)&u)[1] = __floats2half2_rn(r[2], r[3]);
            ((__half2*)&u)[2] = __floats2half2_rn(r[4], r[5]);
            ((__half2*)&u)[3] = __floats2half2_rn(r[6], r[7]);
            *(uint4*)(o + (size_t)node * NCH + c8) = u;
        }
    }
}

// ---------------- tf32 helpers ---------------------------------------------
__device__ __forceinline__ uint32_t f2tf(float x) {
    uint32_t r;
    asm("cvt.rna.tf32.f32 %0, %1;" : "=r"(r) : "f"(x));
    return r;
}

__device__ __forceinline__ void mma_tf32(float* c, uint32_t a0, uint32_t a1,
                                         uint32_t a2, uint32_t a3,
                                         uint32_t b0, uint32_t b1) {
    asm volatile(
        "mma.sync.aligned.m16n8k8.row.col.f32.tf32.tf32.f32 "
        "{%0,%1,%2,%3}, {%4,%5,%6,%7}, {%8,%9}, {%0,%1,%2,%3};"
        : "+f"(c[0]), "+f"(c[1]), "+f"(c[2]), "+f"(c[3])
        : "r"(a0), "r"(a1), "r"(a2), "r"(a3), "r"(b0), "r"(b1));
}

// ---------------- ChebConv GEMM (tf32) + fused relu-stats ------------------
// Y = relu([A0|Tx1|Tx2] @ W + b). Block: 128 nodes x 64 cols, K=192 (6x32).
// term0: fp32 (x or normalized g_Y); term1: T1h * sq[node] (unscale);
// term2: T2h. LAYER 0 also writes prescaled g_Yh.
#define A_P 36
#define B_P 72
template <int LAYER>
__global__ void __launch_bounds__(256)
k_gemm(const float* __restrict__ xp, const float* __restrict__ W,
       const float* __restrict__ bias) {
    __shared__ uint32_t sA[128 * A_P];     // 18432 B
    __shared__ uint32_t sB[32 * B_P];      //  9216 B

    int t = threadIdx.x;
    int lane = t & 31, wm = t >> 5;
    int gid = lane >> 2, tig = lane & 3;
    int nbase = blockIdx.x * 128;

    float acc[8][4];
#pragma unroll
    for (int nt = 0; nt < 8; nt++) {
        float b0 = __ldg(&bias[nt * 8 + 2 * tig]);
        float b1 = __ldg(&bias[nt * 8 + 2 * tig + 1]);
        acc[nt][0] = b0; acc[nt][1] = b1; acc[nt][2] = b0; acc[nt][3] = b1;
    }

#pragma unroll 1
    for (int chunk = 0; chunk < 6; chunk++) {
        int term = chunk >> 1;
        int ch0 = (chunk & 1) * 32;

        if (term == 0) {
            const float* A = (LAYER == 0) ? xp : g_Y;
#pragma unroll
            for (int i = t; i < 1024; i += 256) {
                int nn = i >> 3, q = i & 7;
                int node = nbase + nn;
                float4 v = make_float4(0.f, 0.f, 0.f, 0.f);
                if (node < NN)
                    v = *(const float4*)&A[(size_t)node * NCH + ch0 + q * 4];
                if (LAYER == 1) {
                    float4 m4 = *(const float4*)&g_stats[ch0 + q * 4];
                    float4 r4 = *(const float4*)&g_stats[64 + ch0 + q * 4];
                    v.x = (v.x - m4.x) * r4.x; v.y = (v.y - m4.y) * r4.y;
                    v.z = (v.z - m4.z) * r4.z; v.w = (v.w - m4.w) * r4.w;
                }
                uint32_t* p = &sA[nn * A_P + q * 4];
                p[0] = f2tf(v.x); p[1] = f2tf(v.y);
                p[2] = f2tf(v.z); p[3] = f2tf(v.w);
            }
        } else {
            const __half* A = (term == 1) ? g_T1h : g_T2h;
#pragma unroll
            for (int i = t; i < 512; i += 256) {
                int nn = i >> 2, q = i & 3;       // q covers 8 channels
                int node = nbase + nn;
                uint4 u = make_uint4(0, 0, 0, 0);
                float sc = 1.f;
                if (node < NN) {
                    u = *(const uint4*)(A + (size_t)node * NCH + ch0 + q * 8);
                    if (term == 1) sc = g_sq[node];   // unscale T1h
                }
                float2 f0 = __half22float2(((const __half2*)&u)[0]);
                float2 f1 = __half22float2(((const __half2*)&u)[1]);
                float2 f2 = __half22float2(((const __half2*)&u)[2]);
                float2 f3 = __half22float2(((const __half2*)&u)[3]);
                uint32_t* p = &sA[nn * A_P + q * 8];
                p[0] = f2tf(sc * f0.x); p[1] = f2tf(sc * f0.y);
                p[2] = f2tf(sc * f1.x); p[3] = f2tf(sc * f1.y);
                p[4] = f2tf(sc * f2.x); p[5] = f2tf(sc * f2.y);
                p[6] = f2tf(sc * f3.x); p[7] = f2tf(sc * f3.y);
            }
        }
#pragma unroll
        for (int i = t; i < 512; i += 256) {
            int r = i >> 4, qc = (i & 15) * 4;
            float4 v = *(const float4*)&W[(chunk * 32 + r) * 64 + qc];
            uint32_t* p = &sB[r * B_P + qc];
            p[0] = f2tf(v.x); p[1] = f2tf(v.y);
            p[2] = f2tf(v.z); p[3] = f2tf(v.w);
        }
        __syncthreads();

#pragma unroll
        for (int ks = 0; ks < 4; ks++) {
            int k0 = ks * 8;
            int row0 = wm * 16 + gid;
            uint32_t a0 = sA[row0 * A_P + k0 + tig];
            uint32_t a1 = sA[(row0 + 8) * A_P + k0 + tig];
            uint32_t a2 = sA[row0 * A_P + k0 + tig + 4];
            uint32_t a3 = sA[(row0 + 8) * A_P + k0 + tig + 4];
#pragma unroll
            for (int nt = 0; nt < 8; nt++) {
                uint32_t b0 = sB[(k0 + tig) * B_P + nt * 8 + gid];
                uint32_t b1 = sB[(k0 + tig + 4) * B_P + nt * 8 + gid];
                mma_tf32(acc[nt], a0, a1, a2, a3, b0, b1);
            }
        }
        __syncthreads();
    }

    // relu + writeback (+prescaled fp16 shadow for layer 0) + stats
    int nr0 = nbase + wm * 16 + gid;
    int nr1 = nr0 + 8;
    bool ok0 = nr0 < NN, ok1 = nr1 < NN;
    float dv0 = ok0 ? g_dinv[nr0] : 0.f;
    float dv1 = ok1 ? g_dinv[nr1] : 0.f;
    float* ws = (float*)sB;        // 512 floats
    float* wq = ws + 512;          // 512 floats
#pragma unroll
    for (int nt = 0; nt < 8; nt++) {
        int col = nt * 8 + 2 * tig;
        float a = ok0 ? fmaxf(acc[nt][0], 0.f) : 0.f;
        float b = ok0 ? fmaxf(acc[nt][1], 0.f) : 0.f;
        float c = ok1 ? fmaxf(acc[nt][2], 0.f) : 0.f;
        float d = ok1 ? fmaxf(acc[nt][3], 0.f) : 0.f;
        if (ok0) *(float2*)&g_Y[(size_t)nr0 * NCH + col] = make_float2(a, b);
        if (ok1) *(float2*)&g_Y[(size_t)nr1 * NCH + col] = make_float2(c, d);
        if (LAYER == 0) {
            if (ok0) *(__half2*)&g_Yh[(size_t)nr0 * NCH + col] =
                         __floats2half2_rn(dv0 * a, dv0 * b);
            if (ok1) *(__half2*)&g_Yh[(size_t)nr1 * NCH + col] =
                         __floats2half2_rn(dv1 * c, dv1 * d);
        }
        float s0 = a + c, s1 = b + d;
        float q0 = a * a + c * c, q1 = b * b + d * d;
#pragma unroll
        for (int m = 4; m <= 16; m <<= 1) {
            s0 += __shfl_xor_sync(0xffffffffu, s0, m);
            s1 += __shfl_xor_sync(0xffffffffu, s1, m);
            q0 += __shfl_xor_sync(0xffffffffu, q0, m);
            q1 += __shfl_xor_sync(0xffffffffu, q1, m);
        }
        if (gid == 0) {
            ws[wm * 64 + col]     = s0;
            ws[wm * 64 + col + 1] = s1;
            wq[wm * 64 + col]     = q0;
            wq[wm * 64 + col + 1] = q1;
        }
    }
    __syncthreads();
    if (t < 64) {
        float S = 0.f, Q = 0.f;
#pragma unroll
        for (int w = 0; w < 8; w++) { S += ws[w * 64 + t]; Q += wq[w * 64 + t]; }
        g_part[blockIdx.x * 64 + t] = S;
        g_part[(GB + blockIdx.x) * 64 + t] = Q;
    }
}

// ---------------- stats finalize -------------------------------------------
__global__ void k_stats2() {
    __shared__ float sh[2][1024];
    int c = threadIdx.x & 63, r = threadIdx.x >> 6;   // 16 groups
    float S = 0.f, Q = 0.f;
    for (int b = r; b < GB; b += 16) {
        S += g_part[b * 64 + c];
        Q += g_part[(GB + b) * 64 + c];
    }
    sh[0][threadIdx.x] = S;
    sh[1][threadIdx.x] = Q;
    __syncthreads();
    if (threadIdx.x < 64) {
        float Sf = 0.f, Qf = 0.f;
#pragma unroll
        for (int g = 0; g < 16; g++) {
            Sf += sh[0][g * 64 + c];
            Qf += sh[1][g * 64 + c];
        }
        float m = Sf / (float)NN;
        float var = Qf / (float)NN - m * m;
        g_stats[c] = m;
        g_stats[64 + c] = rsqrtf(var + EPS);
    }
}

// final output norm (layer 2 only)
__global__ void k_norm(float* __restrict__ outp) {
    __shared__ float sm_m[64], sm_r[64];
    if (threadIdx.x < 64) {
        sm_m[threadIdx.x] = g_stats[threadIdx.x];
        sm_r[threadIdx.x] = g_stats[64 + threadIdx.x];
    }
    __syncthreads();
    int i = blockIdx.x * blockDim.x + threadIdx.x;
    int total = NN * (NCH / 4);
    if (i < total) {
        float4 v = ((const float4*)g_Y)[i];
        int q = (i & 15) * 4;
        float4 o;
        o.x = (v.x - sm_m[q + 0]) * sm_r[q + 0];
        o.y = (v.y - sm_m[q + 1]) * sm_r[q + 1];
        o.z = (v.z - sm_m[q + 2]) * sm_r[q + 2];
        o.w = (v.w - sm_m[q + 3]) * sm_r[q + 3];
        ((float4*)outp)[i] = o;
    }
}

// ---------------- launch (kernel launches ONLY — no other CUDA APIs) -------
extern "C" void kernel_launch(void* const* d_in, const int* in_sizes, int n_in,
                              void* d_out, int out_size) {
    const float* x        = (const float*)d_in[0];
    const int* ei         = (const int*)d_in[1];
    const float* W1       = (const float*)d_in[2];
    const float* b1       = (const float*)d_in[3];
    const float* W2       = (const float*)d_in[4];
    const float* b2       = (const float*)d_in[5];
    float* out            = (float*)d_out;

    const int TB = 256;
    int nodeBlocks = (NN + TB - 1) / TB;
    int scaleBlocks = (NN * NCH / 8 + TB - 1) / TB;
    int edge4Blocks = (NE / 4 + TB - 1) / TB;
    int propBlocks = (NN / 4 + 7) / 8;        // ~4 nodes per warp
    int normBlocks = (NN * 16 + TB - 1) / TB;

    // ----- build: zero, fill (counts deg), dinv+sq, prescaled x shadow -----
    k_zero<<<nodeBlocks, TB>>>();
    k_fill<<<edge4Blocks, TB>>>(ei);
    k_dinv<<<nodeBlocks, TB>>>();
    k_scalex<<<scaleBlocks, TB>>>(x);

    // ----- layer 1 -----
    k_prop<0><<<propBlocks, TB>>>(x);
    k_prop<1><<<propBlocks, TB>>>(x);
    k_gemm<0><<<GB, 256>>>(x, W1, b1);
    k_stats2<<<1, 1024>>>();

    // ----- layer 2 (H never materialized; norm fused into consumers) -----
    k_prop<2><<<propBlocks, TB>>>(x);
    k_prop<3><<<propBlocks, TB>>>(x);
    k_gemm<1><<<GB, 256>>>(x, W2, b2);
    k_stats2<<<1, 1024>>>();
    k_norm<<<normBlocks, TB>>>(out);
}

// round 17
// speedup vs baseline: 1.0959x; 1.0157x over previous
#include <cuda_runtime.h>
#include <cuda_fp16.h>
#include <cstdint>

#define NN 100000
#define NE 1600000
#define NCH 64
#define EPS 1e-5f
#define BKT 64                                 // bucket capacity per node
#define GB  ((NN + 127) / 128)                 // 782 gemm blocks

// ---------------- scratch (device globals; no allocation allowed) ----------
__device__ int    g_cnt[NN];
__device__ float  g_dinv[NN];
__device__ float  g_sq[NN];                    // sqrt(deg): unscale factor
__device__ float  g_wsum[NN];                  // sum of dinv[src] per node
__device__ int    g_csrS[(size_t)NN * BKT];    // padded buckets: src only
__device__ float  g_Y[(size_t)NN * NCH];
__device__ __half g_xh[(size_t)NN * NCH];      // PRESCALED dinv*x
__device__ __half g_T1h[(size_t)NN * NCH];     // PRESCALED dinv*Tx1
__device__ __half g_T2h[(size_t)NN * NCH];     // unscaled Tx2 (GEMM only)
__device__ __half g_Yh[(size_t)NN * NCH];      // PRESCALED dinv*relu(Y) L1
__device__ float  g_part[2 * GB * NCH];
__device__ float  g_stats[2 * NCH];

// ---------------- zero counters --------------------------------------------
__global__ void k_zero() {
    int i = blockIdx.x * blockDim.x + threadIdx.x;
    if (i < NN) g_cnt[i] = 0;
}

// ---------------- bucket fill: count + store src, 4 edges/thread -----------
// edge_index is int32 (JAX default x64-disabled demotes int64 -> int32)
__global__ void k_fill(const int* __restrict__ ei) {
    int i = blockIdx.x * blockDim.x + threadIdx.x;
    if (i < NE / 4) {
        int4 s4 = ((const int4*)ei)[i];
        int4 d4 = ((const int4*)(ei + NE))[i];
        int c0 = -1, c1 = -1, c2 = -1, c3 = -1;
        if ((unsigned)s4.x < NN && (unsigned)d4.x < NN)
            c0 = atomicAdd(&g_cnt[d4.x], 1);
        if ((unsigned)s4.y < NN && (unsigned)d4.y < NN)
            c1 = atomicAdd(&g_cnt[d4.y], 1);
        if ((unsigned)s4.z < NN && (unsigned)d4.z < NN)
            c2 = atomicAdd(&g_cnt[d4.z], 1);
        if ((unsigned)s4.w < NN && (unsigned)d4.w < NN)
            c3 = atomicAdd(&g_cnt[d4.w], 1);
        if (c0 >= 0 && c0 < BKT) g_csrS[(size_t)d4.x * BKT + c0] = s4.x;
        if (c1 >= 0 && c1 < BKT) g_csrS[(size_t)d4.y * BKT + c1] = s4.y;
        if (c2 >= 0 && c2 < BKT) g_csrS[(size_t)d4.z * BKT + c2] = s4.z;
        if (c3 >= 0 && c3 < BKT) g_csrS[(size_t)d4.w * BKT + c3] = s4.w;
    }
}

// dinv/sq from counts + prescaled fp16 shadow of x, one kernel
__global__ void k_prep(const float* __restrict__ x) {
    int i = blockIdx.x * blockDim.x + threadIdx.x;   // 8 elems/thread
    if (i < NN * NCH / 8) {
        int node = i >> 3;
        int d = g_cnt[node];
        float dv = (d > 0) ? rsqrtf((float)d) : 0.0f;
        if ((i & 7) == 0) {
            g_dinv[node] = dv;
            g_sq[node] = (d > 0) ? sqrtf((float)d) : 0.0f;
        }
        float4 a = ((const float4*)x)[2 * i];
        float4 b = ((const float4*)x)[2 * i + 1];
        uint4 u;
        ((__half2*)&u)[0] = __floats2half2_rn(dv * a.x, dv * a.y);
        ((__half2*)&u)[1] = __floats2half2_rn(dv * a.z, dv * a.w);
        ((__half2*)&u)[2] = __floats2half2_rn(dv * b.x, dv * b.y);
        ((__half2*)&u)[3] = __floats2half2_rn(dv * b.z, dv * b.w);
        ((uint4*)g_xh)[i] = u;
    }
}

// ---------------- sparse propagation: prescaled fp16 gather ----------------
// 8 warps/block; each warp handles ~4 nodes via grid-stride. Quarter-warp
// (8 lanes) per edge; lane covers 8 channels. Edge pairs pre-summed with
// HADD2 (one fp16 rounding), then converted + fp32-accumulated.
// MODE 0: src=g_xh,  out T1h (prescaled); also computes g_wsum
// MODE 1: src=g_T1h, out T2h, sub=xp fp32
// MODE 2: src=g_Yh,  out T1h (prescaled); uses g_wsum + stats
// MODE 3: src=g_T1h, out T2h, sub=(g_Y-m)*rstd fp32
__device__ __forceinline__ uint32_t hadd2(uint32_t a, uint32_t b) {
    uint32_t r;
    asm("add.f16x2 %0, %1, %2;" : "=r"(r) : "r"(a), "r"(b));
    return r;
}
__device__ __forceinline__ uint4 hadd2x4(uint4 a, uint4 b) {
    uint4 r;
    r.x = hadd2(a.x, b.x); r.y = hadd2(a.y, b.y);
    r.z = hadd2(a.z, b.z); r.w = hadd2(a.w, b.w);
    return r;
}
__device__ __forceinline__ void acc8s(float* a, uint4 p) {
    float2 f0 = __half22float2(((const __half2*)&p)[0]);
    float2 f1 = __half22float2(((const __half2*)&p)[1]);
    float2 f2 = __half22float2(((const __half2*)&p)[2]);
    float2 f3 = __half22float2(((const __half2*)&p)[3]);
    a[0] += f0.x; a[1] += f0.y;
    a[2] += f1.x; a[3] += f1.y;
    a[4] += f2.x; a[5] += f2.y;
    a[6] += f3.x; a[7] += f3.y;
}

template <int MODE>
__global__ void __launch_bounds__(256, 6) k_prop(const float* __restrict__ xp) {
    const __half* hs;
    __half* o;
    if (MODE == 0) { hs = g_xh;  o = g_T1h; }
    if (MODE == 1) { hs = g_T1h; o = g_T2h; }
    if (MODE == 2) { hs = g_Yh;  o = g_T1h; }
    if (MODE == 3) { hs = g_T1h; o = g_T2h; }

    int warpsTotal = gridDim.x * (blockDim.x >> 5);
    int warpId = blockIdx.x * (blockDim.x >> 5) + (threadIdx.x >> 5);
    int lane = threadIdx.x & 31;
    int qtr = lane >> 3;            // 0..3
    int c8 = (lane & 7) * 8;        // channel group (8 ch = 16B fp16)
    const __half* hc8 = hs + c8;

    for (int node = warpId; node < NN; node += warpsTotal) {
        int dg = g_cnt[node];
        if (dg > BKT) dg = BKT;
        int beg = node * BKT, end = beg + dg;

        float a[8] = {0.f, 0.f, 0.f, 0.f, 0.f, 0.f, 0.f, 0.f};
        float wsum = 0.f;
        int j = beg;
        for (; j + 15 < end; j += 16) {
            int4 s = *(const int4*)&g_csrS[j + qtr * 4];
            uint4 p0 = *(const uint4*)(hc8 + (size_t)s.x * NCH);
            uint4 p1 = *(const uint4*)(hc8 + (size_t)s.y * NCH);
            uint4 p2 = *(const uint4*)(hc8 + (size_t)s.z * NCH);
            uint4 p3 = *(const uint4*)(hc8 + (size_t)s.w * NCH);
            acc8s(a, hadd2x4(p0, p1));
            acc8s(a, hadd2x4(p2, p3));
            if (MODE == 0)
                wsum += g_dinv[s.x] + g_dinv[s.y] + g_dinv[s.z] + g_dinv[s.w];
        }
        for (; j + 7 < end; j += 8) {
            int2 s = *(const int2*)&g_csrS[j + qtr * 2];
            uint4 p0 = *(const uint4*)(hc8 + (size_t)s.x * NCH);
            uint4 p1 = *(const uint4*)(hc8 + (size_t)s.y * NCH);
            acc8s(a, hadd2x4(p0, p1));
            if (MODE == 0) wsum += g_dinv[s.x] + g_dinv[s.y];
        }
        for (; j < end; j += 4) {               // tail
            int jj = j + qtr;
            if (jj < end) {
                int s = g_csrS[jj];
                uint4 p = *(const uint4*)(hc8 + (size_t)s * NCH);
                acc8s(a, p);
                if (MODE == 0) wsum += g_dinv[s];
            }
        }
#pragma unroll
        for (int i = 0; i < 8; i++) {
            a[i] += __shfl_xor_sync(0xffffffffu, a[i], 8);
            a[i] += __shfl_xor_sync(0xffffffffu, a[i], 16);
        }
        if (MODE == 0) {
            wsum += __shfl_xor_sync(0xffffffffu, wsum, 8);
            wsum += __shfl_xor_sync(0xffffffffu, wsum, 16);
        }

        if (lane < 8) {
            float dv = g_dinv[node];
            float nd = -dv;
            float r[8];
            if (MODE == 0) {
                if (lane == 0) g_wsum[node] = wsum;
#pragma unroll
                for (int i = 0; i < 8; i++) r[i] = nd * a[i] * dv;
            } else if (MODE == 2) {
                float W = g_wsum[node];
                float4 mA = *(const float4*)(g_stats + c8);
                float4 mB = *(const float4*)(g_stats + c8 + 4);
                float4 rA = *(const float4*)(g_stats + 64 + c8);
                float4 rB = *(const float4*)(g_stats + 64 + c8 + 4);
                r[0] = nd * rA.x * (a[0] - mA.x * W);
                r[1] = nd * rA.y * (a[1] - mA.y * W);
                r[2] = nd * rA.z * (a[2] - mA.z * W);
                r[3] = nd * rA.w * (a[3] - mA.w * W);
                r[4] = nd * rB.x * (a[4] - mB.x * W);
                r[5] = nd * rB.y * (a[5] - mB.y * W);
                r[6] = nd * rB.z * (a[6] - mB.z * W);
                r[7] = nd * rB.w * (a[7] - mB.w * W);
#pragma unroll
                for (int i = 0; i < 8; i++) r[i] *= dv;  // prescale for T1h
            } else if (MODE == 1) {
                float4 s0 = *(const float4*)(xp + (size_t)node * NCH + c8);
                float4 s1 = *(const float4*)(xp + (size_t)node * NCH + c8 + 4);
                float t = 2.f * nd;
                r[0] = t * a[0] - s0.x; r[1] = t * a[1] - s0.y;
                r[2] = t * a[2] - s0.z; r[3] = t * a[3] - s0.w;
                r[4] = t * a[4] - s1.x; r[5] = t * a[5] - s1.y;
                r[6] = t * a[6] - s1.z; r[7] = t * a[7] - s1.w;
            } else { // MODE 3
                float4 s0 = *(const float4*)(g_Y + (size_t)node * NCH + c8);
                float4 s1 = *(const float4*)(g_Y + (size_t)node * NCH + c8 + 4);
                float4 mA = *(const float4*)(g_stats + c8);
                float4 mB = *(const float4*)(g_stats + c8 + 4);
                float4 rA = *(const float4*)(g_stats + 64 + c8);
                float4 rB = *(const float4*)(g_stats + 64 + c8 + 4);
                float t = 2.f * nd;
                r[0] = t * a[0] - (s0.x - mA.x) * rA.x;
                r[1] = t * a[1] - (s0.y - mA.y) * rA.y;
                r[2] = t * a[2] - (s0.z - mA.z) * rA.z;
                r[3] = t * a[3] - (s0.w - mA.w) * rA.w;
                r[4] = t * a[4] - (s1.x - mB.x) * rB.x;
                r[5] = t * a[5] - (s1.y - mB.y) * rB.y;
                r[6] = t * a[6] - (s1.z - mB.z) * rB.z;
                r[7] = t * a[7] - (s1.w - mB.w) * rB.w;
            }
            uint4 u;
            ((__half2*)&u)[0] = __floats2half2_rn(r[0], r[1]);
            ((__half2*)&u)[1] = __floats2half2_rn(r[2], r[3]);
            ((__half2*)&u)[2] = __floats2half2_rn(r[4], r[5]);
            ((__half2*)&u)[3] = __floats2half2_rn(r[6], r[7]);
            *(uint4*)(o + (size_t)node * NCH + c8) = u;
        }
    }
}

// ---------------- tf32 helpers ---------------------------------------------
__device__ __forceinline__ uint32_t f2tf(float x) {
    uint32_t r;
    asm("cvt.rna.tf32.f32 %0, %1;" : "=r"(r) : "f"(x));
    return r;
}

__device__ __forceinline__ void mma_tf32(float* c, uint32_t a0, uint32_t a1,
                                         uint32_t a2, uint32_t a3,
                                         uint32_t b0, uint32_t b1) {
    asm volatile(
        "mma.sync.aligned.m16n8k8.row.col.f32.tf32.tf32.f32 "
        "{%0,%1,%2,%3}, {%4,%5,%6,%7}, {%8,%9}, {%0,%1,%2,%3};"
        : "+f"(c[0]), "+f"(c[1]), "+f"(c[2]), "+f"(c[3])
        : "r"(a0), "r"(a1), "r"(a2), "r"(a3), "r"(b0), "r"(b1));
}

// ---------------- ChebConv GEMM (tf32) + fused relu-stats ------------------
// Y = relu([A0|Tx1|Tx2] @ W + b). Block: 128 nodes x 64 cols, K=192 (6x32).
// term0: fp32 (x or normalized g_Y); term1: T1h * sq[node] (unscale);
// term2: T2h. LAYER 0 also writes prescaled g_Yh.
#define A_P 36
#define B_P 72
template <int LAYER>
__global__ void __launch_bounds__(256)
k_gemm(const float* __restrict__ xp, const float* __restrict__ W,
       const float* __restrict__ bias) {
    __shared__ uint32_t sA[128 * A_P];     // 18432 B
    __shared__ uint32_t sB[32 * B_P];      //  9216 B

    int t = threadIdx.x;
    int lane = t & 31, wm = t >> 5;
    int gid = lane >> 2, tig = lane & 3;
    int nbase = blockIdx.x * 128;

    float acc[8][4];
#pragma unroll
    for (int nt = 0; nt < 8; nt++) {
        float b0 = __ldg(&bias[nt * 8 + 2 * tig]);
        float b1 = __ldg(&bias[nt * 8 + 2 * tig + 1]);
        acc[nt][0] = b0; acc[nt][1] = b1; acc[nt][2] = b0; acc[nt][3] = b1;
    }

#pragma unroll 1
    for (int chunk = 0; chunk < 6; chunk++) {
        int term = chunk >> 1;
        int ch0 = (chunk & 1) * 32;

        if (term == 0) {
            const float* A = (LAYER == 0) ? xp : g_Y;
#pragma unroll
            for (int i = t; i < 1024; i += 256) {
                int nn = i >> 3, q = i & 7;
                int node = nbase + nn;
                float4 v = make_float4(0.f, 0.f, 0.f, 0.f);
                if (node < NN)
                    v = *(const float4*)&A[(size_t)node * NCH + ch0 + q * 4];
                if (LAYER == 1) {
                    float4 m4 = *(const float4*)&g_stats[ch0 + q * 4];
                    float4 r4 = *(const float4*)&g_stats[64 + ch0 + q * 4];
                    v.x = (v.x - m4.x) * r4.x; v.y = (v.y - m4.y) * r4.y;
                    v.z = (v.z - m4.z) * r4.z; v.w = (v.w - m4.w) * r4.w;
                }
                uint32_t* p = &sA[nn * A_P + q * 4];
                p[0] = f2tf(v.x); p[1] = f2tf(v.y);
                p[2] = f2tf(v.z); p[3] = f2tf(v.w);
            }
        } else {
            const __half* A = (term == 1) ? g_T1h : g_T2h;
#pragma unroll
            for (int i = t; i < 512; i += 256) {
                int nn = i >> 2, q = i & 3;       // q covers 8 channels
                int node = nbase + nn;
                uint4 u = make_uint4(0, 0, 0, 0);
                float sc = 1.f;
                if (node < NN) {
                    u = *(const uint4*)(A + (size_t)node * NCH + ch0 + q * 8);
                    if (term == 1) sc = g_sq[node];   // unscale T1h
                }
                float2 f0 = __half22float2(((const __half2*)&u)[0]);
                float2 f1 = __half22float2(((const __half2*)&u)[1]);
                float2 f2 = __half22float2(((const __half2*)&u)[2]);
                float2 f3 = __half22float2(((const __half2*)&u)[3]);
                uint32_t* p = &sA[nn * A_P + q * 8];
                p[0] = f2tf(sc * f0.x); p[1] = f2tf(sc * f0.y);
                p[2] = f2tf(sc * f1.x); p[3] = f2tf(sc * f1.y);
                p[4] = f2tf(sc * f2.x); p[5] = f2tf(sc * f2.y);
                p[6] = f2tf(sc * f3.x); p[7] = f2tf(sc * f3.y);
            }
        }
#pragma unroll
        for (int i = t; i < 512; i += 256) {
            int r = i >> 4, qc = (i & 15) * 4;
            float4 v = *(const float4*)&W[(chunk * 32 + r) * 64 + qc];
            uint32_t* p = &sB[r * B_P + qc];
            p[0] = f2tf(v.x); p[1] = f2tf(v.y);
            p[2] = f2tf(v.z); p[3] = f2tf(v.w);
        }
        __syncthreads();

#pragma unroll
        for (int ks = 0; ks < 4; ks++) {
            int k0 = ks * 8;
            int row0 = wm * 16 + gid;
            uint32_t a0 = sA[row0 * A_P + k0 + tig];
            uint32_t a1 = sA[(row0 + 8) * A_P + k0 + tig];
            uint32_t a2 = sA[row0 * A_P + k0 + tig + 4];
            uint32_t a3 = sA[(row0 + 8) * A_P + k0 + tig + 4];
#pragma unroll
            for (int nt = 0; nt < 8; nt++) {
                uint32_t b0 = sB[(k0 + tig) * B_P + nt * 8 + gid];
                uint32_t b1 = sB[(k0 + tig + 4) * B_P + nt * 8 + gid];
                mma_tf32(acc[nt], a0, a1, a2, a3, b0, b1);
            }
        }
        __syncthreads();
    }

    // relu + writeback (+prescaled fp16 shadow for layer 0) + stats
    int nr0 = nbase + wm * 16 + gid;
    int nr1 = nr0 + 8;
    bool ok0 = nr0 < NN, ok1 = nr1 < NN;
    float dv0 = ok0 ? g_dinv[nr0] : 0.f;
    float dv1 = ok1 ? g_dinv[nr1] : 0.f;
    float* ws = (float*)sB;        // 512 floats
    float* wq = ws + 512;          // 512 floats
#pragma unroll
    for (int nt = 0; nt < 8; nt++) {
        int col = nt * 8 + 2 * tig;
        float a = ok0 ? fmaxf(acc[nt][0], 0.f) : 0.f;
        float b = ok0 ? fmaxf(acc[nt][1], 0.f) : 0.f;
        float c = ok1 ? fmaxf(acc[nt][2], 0.f) : 0.f;
        float d = ok1 ? fmaxf(acc[nt][3], 0.f) : 0.f;
        if (ok0) *(float2*)&g_Y[(size_t)nr0 * NCH + col] = make_float2(a, b);
        if (ok1) *(float2*)&g_Y[(size_t)nr1 * NCH + col] = make_float2(c, d);
        if (LAYER == 0) {
            if (ok0) *(__half2*)&g_Yh[(size_t)nr0 * NCH + col] =
                         __floats2half2_rn(dv0 * a, dv0 * b);
            if (ok1) *(__half2*)&g_Yh[(size_t)nr1 * NCH + col] =
                         __floats2half2_rn(dv1 * c, dv1 * d);
        }
        float s0 = a + c, s1 = b + d;
        float q0 = a * a + c * c, q1 = b * b + d * d;
#pragma unroll
        for (int m = 4; m <= 16; m <<= 1) {
            s0 += __shfl_xor_sync(0xffffffffu, s0, m);
            s1 += __shfl_xor_sync(0xffffffffu, s1, m);
            q0 += __shfl_xor_sync(0xffffffffu, q0, m);
            q1 += __shfl_xor_sync(0xffffffffu, q1, m);
        }
        if (gid == 0) {
            ws[wm * 64 + col]     = s0;
            ws[wm * 64 + col + 1] = s1;
            wq[wm * 64 + col]     = q0;
            wq[wm * 64 + col + 1] = q1;
        }
    }
    __syncthreads();
    if (t < 64) {
        float S = 0.f, Q = 0.f;
#pragma unroll
        for (int w = 0; w < 8; w++) { S += ws[w * 64 + t]; Q += wq[w * 64 + t]; }
        g_part[blockIdx.x * 64 + t] = S;
        g_part[(GB + blockIdx.x) * 64 + t] = Q;
    }
}

// ---------------- stats finalize -------------------------------------------
__global__ void k_stats2() {
    __shared__ float sh[2][1024];
    int c = threadIdx.x & 63, r = threadIdx.x >> 6;   // 16 groups
    float S = 0.f, Q = 0.f;
    for (int b = r; b < GB; b += 16) {
        S += g_part[b * 64 + c];
        Q += g_part[(GB + b) * 64 + c];
    }
    sh[0][threadIdx.x] = S;
    sh[1][threadIdx.x] = Q;
    __syncthreads();
    if (threadIdx.x < 64) {
        float Sf = 0.f, Qf = 0.f;
#pragma unroll
        for (int g = 0; g < 16; g++) {
            Sf += sh[0][g * 64 + c];
            Qf += sh[1][g * 64 + c];
        }
        float m = Sf / (float)NN;
        float var = Qf / (float)NN - m * m;
        g_stats[c] = m;
        g_stats[64 + c] = rsqrtf(var + EPS);
    }
}

// final output norm (layer 2 only)
__global__ void k_norm(float* __restrict__ outp) {
    __shared__ float sm_m[64], sm_r[64];
    if (threadIdx.x < 64) {
        sm_m[threadIdx.x] = g_stats[threadIdx.x];
        sm_r[threadIdx.x] = g_stats[64 + threadIdx.x];
    }
    __syncthreads();
    int i = blockIdx.x * blockDim.x + threadIdx.x;
    int total = NN * (NCH / 4);
    if (i < total) {
        float4 v = ((const float4*)g_Y)[i];
        int q = (i & 15) * 4;
        float4 o;
        o.x = (v.x - sm_m[q + 0]) * sm_r[q + 0];
        o.y = (v.y - sm_m[q + 1]) * sm_r[q + 1];
        o.z = (v.z - sm_m[q + 2]) * sm_r[q + 2];
        o.w = (v.w - sm_m[q + 3]) * sm_r[q + 3];
        ((float4*)outp)[i] = o;
    }
}

// ---------------- launch (kernel launches ONLY — no other CUDA APIs) -------
extern "C" void kernel_launch(void* const* d_in, const int* in_sizes, int n_in,
                              void* d_out, int out_size) {
    const float* x        = (const float*)d_in[0];
    const int* ei         = (const int*)d_in[1];
    const float* W1       = (const float*)d_in[2];
    const float* b1       = (const float*)d_in[3];
    const float* W2       = (const float*)d_in[4];
    const float* b2       = (const float*)d_in[5];
    float* out            = (float*)d_out;

    const int TB = 256;
    int nodeBlocks = (NN + TB - 1) / TB;
    int prepBlocks = (NN * NCH / 8 + TB - 1) / TB;
    int edge4Blocks = (NE / 4 + TB - 1) / TB;
    int propBlocks = (NN / 4 + 7) / 8;        // ~4 nodes per warp
    int normBlocks = (NN * 16 + TB - 1) / TB;

    // ----- build: zero, fill (counts deg), prep (dinv/sq + x shadow) -----
    k_zero<<<nodeBlocks, TB>>>();
    k_fill<<<edge4Blocks, TB>>>(ei);
    k_prep<<<prepBlocks, TB>>>(x);

    // ----- layer 1 -----
    k_prop<0><<<propBlocks, TB>>>(x);
    k_prop<1><<<propBlocks, TB>>>(x);
    k_gemm<0><<<GB, 256>>>(x, W1, b1);
    k_stats2<<<1, 1024>>>();

    // ----- layer 2 (H never materialized; norm fused into consumers) -----
    k_prop<2><<<propBlocks, TB>>>(x);
    k_prop<3><<<propBlocks, TB>>>(x);
    k_gemm<1><<<GB, 256>>>(x, W2, b2);
    k_stats2<<<1, 1024>>>();
    k_norm<<<normBlocks, TB>>>(out);
}